// round 13
// baseline (speedup 1.0000x reference)
#include <cuda_runtime.h>

// Problem constants
#define TD     64
#define MODES  16
#define MRI    32          // 2*MODES
#define PD     16384       // N*D pixels
#define SCOL   1048576     // PD*64 floats per time row
#define TILE_P 8
#define NBLK   (PD / TILE_P)   // 2048 CTAs
#define NTHR   256
#define PXS    33          // u64 stride per pixel row (32 + 1 pad -> bank spread)

typedef unsigned long long u64;

// Packed, transposed weights: g_W[m][c2][o] = ( (WR[2c2],WR[2c2+1]), (WI[2c2],WI[2c2+1]) )
__device__ ulonglong2 g_W[MODES * 32 * 64];   // 512 KB

// ---------- compile-time DFT coefficients ----------
__host__ __device__ constexpr float cos64(int k) {
    constexpr float COSQ[17] = {
        1.0f,
        0.995184726672197f, 0.980785280403230f, 0.956940335732209f,
        0.923879532511287f, 0.881921264348355f, 0.831469612302545f,
        0.773010453362737f, 0.707106781186548f, 0.634393284163645f,
        0.555570233019602f, 0.471396736825998f, 0.382683432365090f,
        0.290284677254462f, 0.195090322016128f, 0.098017140329561f,
        0.0f
    };
    k &= 63;
    float s = 1.0f;
    if (k > 32) k = 64 - k;
    if (k > 16) { k = 32 - k; s = -1.0f; }
    return s * COSQ[k];
}
__host__ __device__ constexpr float alpha64(int m) {
    return ((m == 0) ? 1.0f : 2.0f) / 64.0f;
}

// ---------- packed f32x2 helpers ----------
__device__ __forceinline__ u64 pack2(float a, float b) {
    u64 r;
    asm("mov.b64 %0, {%1, %2};" : "=l"(r) : "f"(a), "f"(b));
    return r;
}
__device__ __forceinline__ void unpack2(u64 v, float &lo, float &hi) {
    asm("mov.b64 {%0, %1}, %2;" : "=f"(lo), "=f"(hi) : "l"(v));
}
__device__ __forceinline__ void fma2(u64 &d, u64 a, u64 b) {
    asm("fma.rn.f32x2 %0, %1, %2, %0;" : "+l"(d) : "l"(a), "l"(b));
}
__device__ __forceinline__ float hadd(u64 v) {
    float lo, hi;
    unpack2(v, lo, hi);
    return lo + hi;
}

// =====================================================================
// One-time weight repack: w[c][o][m][2]  ->  g_W[m][c2][o]
// =====================================================================
__global__ void __launch_bounds__(256) w_pack(const float* __restrict__ w) {
    int idx = blockIdx.x * 256 + threadIdx.x;     // 0 .. 32767
    int m  = idx >> 11;
    int c2 = (idx >> 6) & 31;
    int o  = idx & 63;
    int c0 = 2 * c2;
    const float* b0 = w + ((((c0    ) * 64 + o) * MODES + m) << 1);
    const float* b1 = w + ((((c0 + 1) * 64 + o) * MODES + m) << 1);
    ulonglong2 v;
    v.x = pack2(b0[0], b1[0]);
    v.y = pack2(b0[1], b1[1]);
    g_W[idx] = v;
}

// =====================================================================
// Fused spectral conv. 256 threads, 8 pixels per CTA, 98 KB smem,
// 2 CTAs per SM (barrier/latency overlap across CTAs).
// smem layout (bytes):
//   [0     , 67584 ) XY  [mri][8p][33 u64] — px rows padded to 264B;
//                    X, overwritten in-place per mode by Y
//   [67584 ,100352 ) W   [c2][o] ulonglong2 (single buffer, 32 KB)
// Stage 2 warp tile: 8px x 8o (lane = 1 px, 2 strided outputs).
// =====================================================================
__global__ void __launch_bounds__(NTHR, 2) fused_spectral(const float* __restrict__ x,
                                                          float* __restrict__ out) {
    extern __shared__ __align__(16) char smem[];
    u64*        XY64 = reinterpret_cast<u64*>(smem);
    float*      XYf  = reinterpret_cast<float*>(smem);
    ulonglong2* Wc   = reinterpret_cast<ulonglong2*>(smem + 67584);

    const int tid = threadIdx.x;
    const int p0  = blockIdx.x * TILE_P;

    // ---- prefetch W for mode 0 (overlaps with stage 1 gmem reads) ----
    ulonglong2 wreg[8];
#pragma unroll
    for (int k = 0; k < 8; k++) wreg[k] = g_W[tid + k * NTHR];

    // =============== Stage 1: truncated rfft into smem (folded) ===============
    // 8 warps = 8 pixels; lane = channel pair. Single pass.
    {
        const int cp = tid & 31;
        const int p  = tid >> 5;           // 0..7, warp-uniform
        const u64* xp = reinterpret_cast<const u64*>(x) + (long)(p0 + p) * 32 + cp;

        float XcL[16], XcH[16], XsL[16], XsH[16];
        {
            float x0L, x0H, x32L, x32H;
            unpack2(xp[0], x0L, x0H);
            unpack2(xp[32 * (SCOL / 2)], x32L, x32H);
#pragma unroll
            for (int m = 0; m < 16; m++) {
                if (m & 1) { XcL[m] = x0L - x32L; XcH[m] = x0H - x32H; }
                else       { XcL[m] = x0L + x32L; XcH[m] = x0H + x32H; }
                XsL[m] = 0.0f; XsH[m] = 0.0f;
            }
        }

#pragma unroll
        for (int t = 1; t < 32; t++) {
            float aL, aH, bL, bH;
            unpack2(xp[(long)t * (SCOL / 2)], aL, aH);
            unpack2(xp[(long)(64 - t) * (SCOL / 2)], bL, bH);
            const float eL = aL + bL, eH = aH + bH;
            const float oL = aL - bL, oH = aH - bH;
            XcL[0] += eL; XcH[0] += eH;
#pragma unroll
            for (int m = 1; m < 16; m++) {
                const float fc = cos64(m * t);
                const float fs = cos64(m * t + 16);
                if (fc != 0.0f) {
                    XcL[m] = fmaf(eL, fc, XcL[m]);
                    XcH[m] = fmaf(eH, fc, XcH[m]);
                }
                if (fs != 0.0f) {
                    XsL[m] = fmaf(oL, fs, XsL[m]);
                    XsH[m] = fmaf(oH, fs, XsH[m]);
                }
            }
        }

#pragma unroll
        for (int m = 0; m < 16; m++) {
            XY64[((2 * m)     * TILE_P + p) * PXS + cp] = pack2(XcL[m], XcH[m]);
            XY64[((2 * m + 1) * TILE_P + p) * PXS + cp] = pack2(XsL[m], XsH[m]);
        }
        // published at the first syncthreads inside the mode loop
    }

    // =============== Stage 2: per-mode complex channel mix ===============
    // Warp tile 8px x 8o. lane = pxi(8) x osub(4); o = og*8 + osub + 4j, j<2.
    // W single buffer: sync(A) orders STS W before reads; sync(B) orders
    // reads before next mode's STS overwrite.
    {
        const int lane  = tid & 31;
        const int og    = tid >> 5;               // 0..7
        const int px    = lane & 7;
        const int osub  = lane >> 3;              // 0..3
        const int obase = og * 8 + osub;          // o = obase + 4j

        for (int m = 0; m < MODES; m++) {
#pragma unroll
            for (int k = 0; k < 8; k++) Wc[tid + k * NTHR] = wreg[k];
            __syncthreads();   // (A) W_m visible; publishes X (m=0) / Y_{m-1}

            if (m < MODES - 1) {
#pragma unroll
                for (int k = 0; k < 8; k++)
                    wreg[k] = g_W[(m + 1) * 2048 + tid + k * NTHR];
            }

            const u64* xRrow = XY64 + ((2 * m)     * TILE_P + px) * PXS;
            const u64* xIrow = XY64 + ((2 * m + 1) * TILE_P + px) * PXS;

            // P = sum xr*wr, Q = sum xi*wi, T = sum (xr*wi + xi*wr)
            u64 P[2], Q[2], T[2];
#pragma unroll
            for (int j = 0; j < 2; j++) { P[j] = 0; Q[j] = 0; T[j] = 0; }

#pragma unroll 8
            for (int c2 = 0; c2 < 32; c2++) {
                u64 xr = xRrow[c2];                // LDS.64, 8 distinct, 1 wf
                u64 xi = xIrow[c2];
#pragma unroll
                for (int j = 0; j < 2; j++) {
                    ulonglong2 wv = Wc[(c2 << 6) + obase + 4 * j];  // LDS.128, 1 wf
                    fma2(P[j], xr, wv.x);
                    fma2(Q[j], xi, wv.y);
                    fma2(T[j], xr, wv.y);
                    fma2(T[j], xi, wv.x);
                }
            }

            __syncthreads();   // (B) all reads of X_m / W_m complete

#pragma unroll
            for (int j = 0; j < 2; j++) {
                const int o = obase + 4 * j;
                float yr = hadd(P[j]) - hadd(Q[j]);
                float yi = hadd(T[j]);
                XYf[(((2 * m)     * TILE_P + px) * PXS) * 2 + o] = yr;
                XYf[(((2 * m + 1) * TILE_P + px) * PXS) * 2 + o] = yi;
            }
        }
    }
    __syncthreads();   // Y complete

    // =============== Stage 3: truncated irfft from smem (folded) ===============
    // 8 warps = 8 pixels; lane = output pair. Single pass.
    {
        const int op = tid & 31;
        const int p  = tid >> 5;

        float yRL[16], yRH[16], yIL[16], yIH[16];
#pragma unroll
        for (int m = 0; m < 16; m++) {
            unpack2(XY64[((2 * m)     * TILE_P + p) * PXS + op], yRL[m], yRH[m]);
            unpack2(XY64[((2 * m + 1) * TILE_P + p) * PXS + op], yIL[m], yIH[m]);
        }

        u64* outp = reinterpret_cast<u64*>(out) + (long)(p0 + p) * 32 + op;

        // t = 0
        {
            float c0 = 0.0f, c1 = 0.0f;
#pragma unroll
            for (int m = 0; m < 16; m++) {
                const float g = alpha64(m);
                c0 = fmaf(yRL[m], g, c0);
                c1 = fmaf(yRH[m], g, c1);
            }
            outp[0] = pack2(c0, c1);
        }
        // t = 32
        {
            float c0 = 0.0f, c1 = 0.0f;
#pragma unroll
            for (int m = 0; m < 16; m++) {
                const float g = (m & 1) ? -alpha64(m) : alpha64(m);
                c0 = fmaf(yRL[m], g, c0);
                c1 = fmaf(yRH[m], g, c1);
            }
            outp[32 * (SCOL / 2)] = pack2(c0, c1);
        }

#pragma unroll
        for (int t = 1; t < 32; t++) {
            float C0 = 0.0f, C1 = 0.0f, S0 = 0.0f, S1 = 0.0f;
#pragma unroll
            for (int m = 0; m < 16; m++) {
                const float gc = alpha64(m) * cos64(m * t);
                const float gs = alpha64(m) * cos64(m * t + 16);
                if (gc != 0.0f) {
                    C0 = fmaf(yRL[m], gc, C0);
                    C1 = fmaf(yRH[m], gc, C1);
                }
                if (gs != 0.0f) {
                    S0 = fmaf(yIL[m], gs, S0);
                    S1 = fmaf(yIH[m], gs, S1);
                }
            }
            outp[(long)t * (SCOL / 2)]        = pack2(C0 + S0, C1 + S1);
            outp[(long)(64 - t) * (SCOL / 2)] = pack2(C0 - S0, C1 - S1);
        }
    }
}

// =====================================================================
extern "C" void kernel_launch(void* const* d_in, const int* in_sizes, int n_in,
                              void* d_out, int out_size) {
    const float* x = (const float*)d_in[0];   // [64][1024][16][64] f32
    const float* w = (const float*)d_in[1];   // [64][64][16][2] f32
    float* out     = (float*)d_out;           // [64][1024][16][64] f32
    (void)in_sizes; (void)n_in; (void)out_size;

    cudaFuncSetAttribute(fused_spectral, cudaFuncAttributeMaxDynamicSharedMemorySize, 100352);

    w_pack<<<128, 256>>>(w);
    fused_spectral<<<NBLK, NTHR, 100352>>>(x, out);
}

// round 14
// speedup vs baseline: 1.7059x; 1.7059x over previous
#include <cuda_runtime.h>
#include <cstdint>

// Problem constants
#define TD     64
#define MODES  16
#define MRI    32          // 2*MODES
#define PD     16384       // N*D pixels
#define SCOL   1048576     // PD*64 floats per time row
#define TILE_P 16
#define NBLK   (PD / TILE_P)   // 1024 CTAs
#define NTHR   256

typedef unsigned long long u64;

// tf32-rounded, k-permuted, n-swizzled weights, exact smem image per mode:
// g_W3f[m][comp][n][ S(k) ^ ((n&3)<<3) ], comp 0=WR, 1=WI.  512 KB.
__device__ __align__(16) float g_W3f[MODES * 2 * 64 * 64];

// ---------- compile-time DFT coefficients ----------
__host__ __device__ constexpr float cos64(int k) {
    constexpr float COSQ[17] = {
        1.0f,
        0.995184726672197f, 0.980785280403230f, 0.956940335732209f,
        0.923879532511287f, 0.881921264348355f, 0.831469612302545f,
        0.773010453362737f, 0.707106781186548f, 0.634393284163645f,
        0.555570233019602f, 0.471396736825998f, 0.382683432365090f,
        0.290284677254462f, 0.195090322016128f, 0.098017140329561f,
        0.0f
    };
    k &= 63;
    float s = 1.0f;
    if (k > 32) k = 64 - k;
    if (k > 16) { k = 32 - k; s = -1.0f; }
    return s * COSQ[k];
}
__host__ __device__ constexpr float alpha64(int m) {
    return ((m == 0) ? 1.0f : 2.0f) / 64.0f;
}

// mma-fragment channel permutation within each 8-wide k-tile:
// logical r<4 -> 2r ; r>=4 -> 2(r-4)+1   (pairs (t, t+4) become adjacent)
__host__ __device__ __forceinline__ int SPERM(int c) {
    int r = c & 7;
    int s = (r < 4) ? (2 * r) : (2 * (r - 4) + 1);
    return (c & ~7) | s;
}

// ---------- helpers ----------
__device__ __forceinline__ u64 pack2(float a, float b) {
    u64 r;
    asm("mov.b64 %0, {%1, %2};" : "=l"(r) : "f"(a), "f"(b));
    return r;
}
__device__ __forceinline__ void unpack2(u64 v, float &lo, float &hi) {
    asm("mov.b64 {%0, %1}, %2;" : "=f"(lo), "=f"(hi) : "l"(v));
}
__device__ __forceinline__ uint32_t f2tf32(float x) {
    uint32_t r;
    asm("cvt.rna.tf32.f32 %0, %1;" : "=r"(r) : "f"(x));
    return r;
}
__device__ __forceinline__ void mma_tf32(float d[4],
                                         uint32_t a0, uint32_t a1, uint32_t a2, uint32_t a3,
                                         uint32_t b0, uint32_t b1) {
    asm("mma.sync.aligned.m16n8k8.row.col.f32.tf32.tf32.f32 "
        "{%0,%1,%2,%3},{%4,%5,%6,%7},{%8,%9},{%0,%1,%2,%3};"
        : "+f"(d[0]), "+f"(d[1]), "+f"(d[2]), "+f"(d[3])
        : "r"(a0), "r"(a1), "r"(a2), "r"(a3), "r"(b0), "r"(b1));
}

// =====================================================================
// One-time weight repack into the per-mode smem image.
// =====================================================================
__global__ void __launch_bounds__(256) w_pack(const float* __restrict__ w) {
    int idx = blockIdx.x * 256 + threadIdx.x;         // 0 .. 131071
    int m    = idx >> 13;
    int comp = (idx >> 12) & 1;
    int n    = (idx >> 6) & 63;
    int k    = idx & 63;
    float v = w[(((long)k * 64 + n) * MODES + m) * 2 + comp];
    int dst = m * 8192 + (comp * 64 + n) * 64 + (SPERM(k) ^ ((n & 3) << 3));
    reinterpret_cast<uint32_t*>(g_W3f)[dst] = f2tf32(v);
}

// =====================================================================
// Fused spectral conv. 256 threads, 16 pixels/CTA, 192 KB smem.
// smem:
//   [0      ,131072 ) XY [32 mri][16 px][64 f32]
//       X rows: tf32 bits, k-permuted cols, XOR-swizzled by (px&3)<<3
//       Y rows: f32, logical cols, XOR-swizzled by (px&3)<<3 (u64 pairs)
//   [131072 ,163840 ) W buf 0 (per-mode image: [comp][n][perm+swz k])
//   [163840 ,196608 ) W buf 1
// Stage 2: mma.sync m16n8k8 tf32; warp = n-tile; lane: g=lane>>2, t=lane&3.
// =====================================================================
__global__ void __launch_bounds__(NTHR, 1) fused_spectral(const float* __restrict__ x,
                                                          float* __restrict__ out) {
    extern __shared__ __align__(16) char smem[];
    u64*        XY64 = reinterpret_cast<u64*>(smem);
    uint32_t*   XYu  = reinterpret_cast<uint32_t*>(smem);
    ulonglong2* Wst0 = reinterpret_cast<ulonglong2*>(smem + 131072);
    ulonglong2* Wst1 = reinterpret_cast<ulonglong2*>(smem + 163840);
    const u64*  Wc0  = reinterpret_cast<const u64*>(smem + 131072);
    const u64*  Wc1  = reinterpret_cast<const u64*>(smem + 163840);

    const int tid = threadIdx.x;
    const int p0  = blockIdx.x * TILE_P;

    const ulonglong2* gW = reinterpret_cast<const ulonglong2*>(g_W3f);

    // ---- prefetch W for mode 0 ----
    ulonglong2 wreg[8];
#pragma unroll
    for (int k = 0; k < 8; k++) wreg[k] = gW[tid + k * NTHR];

    // =============== Stage 1: truncated rfft (folded, FFMA-imm) ===============
    // Stores tf32-rounded X in permuted+swizzled layout for mma A-fragments.
    {
        const int cp = tid & 31;
        const int pp = tid >> 5;
        const int s0 = SPERM(2 * cp);        // storage col of logical channel 2cp
        const int s1 = SPERM(2 * cp + 1);

        for (int pass = 0; pass < 2; pass++) {
            const int p   = pp + pass * 8;
            const int swz = (p & 3) << 3;
            const u64* xp = reinterpret_cast<const u64*>(x) + (long)(p0 + p) * 32 + cp;

            float XcL[16], XcH[16], XsL[16], XsH[16];
            {
                float x0L, x0H, x32L, x32H;
                unpack2(xp[0], x0L, x0H);
                unpack2(xp[32 * (SCOL / 2)], x32L, x32H);
#pragma unroll
                for (int m = 0; m < 16; m++) {
                    if (m & 1) { XcL[m] = x0L - x32L; XcH[m] = x0H - x32H; }
                    else       { XcL[m] = x0L + x32L; XcH[m] = x0H + x32H; }
                    XsL[m] = 0.0f; XsH[m] = 0.0f;
                }
            }

#pragma unroll
            for (int t = 1; t < 32; t++) {
                float aL, aH, bL, bH;
                unpack2(xp[(long)t * (SCOL / 2)], aL, aH);
                unpack2(xp[(long)(64 - t) * (SCOL / 2)], bL, bH);
                const float eL = aL + bL, eH = aH + bH;
                const float oL = aL - bL, oH = aH - bH;
                XcL[0] += eL; XcH[0] += eH;
#pragma unroll
                for (int m = 1; m < 16; m++) {
                    const float fc = cos64(m * t);
                    const float fs = cos64(m * t + 16);
                    if (fc != 0.0f) {
                        XcL[m] = fmaf(eL, fc, XcL[m]);
                        XcH[m] = fmaf(eH, fc, XcH[m]);
                    }
                    if (fs != 0.0f) {
                        XsL[m] = fmaf(oL, fs, XsL[m]);
                        XsH[m] = fmaf(oH, fs, XsH[m]);
                    }
                }
            }

#pragma unroll
            for (int m = 0; m < 16; m++) {
                const int rowR = ((2 * m)     * TILE_P + p) * 64;
                const int rowI = ((2 * m + 1) * TILE_P + p) * 64;
                XYu[rowR + (s0 ^ swz)] = f2tf32(XcL[m]);
                XYu[rowR + (s1 ^ swz)] = f2tf32(XcH[m]);
                XYu[rowI + (s0 ^ swz)] = f2tf32(XsL[m]);
                XYu[rowI + (s1 ^ swz)] = f2tf32(XsH[m]);
            }
        }
        // published at the first syncthreads inside the mode loop
    }

    // =============== Stage 2: per-mode complex channel mix (tensor) ===============
    // Warp = n-tile (8 outputs). YR = XR*WR + XI*(-WI); YI = XR*WI + XI*WR.
    {
        const int lane = tid & 31;
        const int nt   = tid >> 5;          // n-tile 0..7
        const int g    = lane >> 2;         // 0..7
        const int t    = lane & 3;          // 0..3
        const int swzg = (g & 3) << 2;      // u64-index XOR (px rows g/g+8; W n rows)

        for (int m = 0; m < MODES; m++) {
            ulonglong2* Wst = (m & 1) ? Wst1 : Wst0;
#pragma unroll
            for (int k = 0; k < 8; k++) Wst[tid + k * NTHR] = wreg[k];
            __syncthreads();   // W_m visible; publishes X (m=0) / Y_{m-1}

            if (m < MODES - 1) {
#pragma unroll
                for (int k = 0; k < 8; k++)
                    wreg[k] = gW[(m + 1) * 2048 + tid + k * NTHR];
            }

            const u64* Wc = (m & 1) ? Wc1 : Wc0;
            const int rowR = (2 * m)     * TILE_P * 32;   // u64 base of XR rows
            const int rowI = (2 * m + 1) * TILE_P * 32;

            float dR[4] = {0.f, 0.f, 0.f, 0.f};
            float dI[4] = {0.f, 0.f, 0.f, 0.f};

#pragma unroll
            for (int kt = 0; kt < 8; kt++) {
                const int col = (kt * 4 + t) ^ swzg;
                u64 ar0 = XY64[rowR + g * 32 + col];         // A: rows g / g+8
                u64 ar1 = XY64[rowR + (g + 8) * 32 + col];
                u64 ai0 = XY64[rowI + g * 32 + col];
                u64 ai1 = XY64[rowI + (g + 8) * 32 + col];
                u64 br  = Wc[(nt * 8 + g) * 32 + col];       // B: WR
                u64 bi  = Wc[(64 + nt * 8 + g) * 32 + col];  // B: WI
                u64 bn  = bi ^ 0x8000000080000000ULL;        // -WI

                uint2 AR0 = *reinterpret_cast<uint2*>(&ar0); // (a0, a2)
                uint2 AR1 = *reinterpret_cast<uint2*>(&ar1); // (a1, a3)
                uint2 AI0 = *reinterpret_cast<uint2*>(&ai0);
                uint2 AI1 = *reinterpret_cast<uint2*>(&ai1);
                uint2 BR  = *reinterpret_cast<uint2*>(&br);  // (b0, b1)
                uint2 BI  = *reinterpret_cast<uint2*>(&bi);
                uint2 BN  = *reinterpret_cast<uint2*>(&bn);

                mma_tf32(dR, AR0.x, AR1.x, AR0.y, AR1.y, BR.x, BR.y);
                mma_tf32(dR, AI0.x, AI1.x, AI0.y, AI1.y, BN.x, BN.y);
                mma_tf32(dI, AR0.x, AR1.x, AR0.y, AR1.y, BI.x, BI.y);
                mma_tf32(dI, AI0.x, AI1.x, AI0.y, AI1.y, BR.x, BR.y);
            }

            __syncthreads();   // all reads of X_m / W_m complete before overwrite

            // Epilogue: Y in logical cols (o = nt*8 + 2t, 2t+1), px-swizzled.
            const int ecol = (nt * 4 + t) ^ swzg;
            XY64[rowR + g * 32 + ecol]       = pack2(dR[0], dR[1]);
            XY64[rowR + (g + 8) * 32 + ecol] = pack2(dR[2], dR[3]);
            XY64[rowI + g * 32 + ecol]       = pack2(dI[0], dI[1]);
            XY64[rowI + (g + 8) * 32 + ecol] = pack2(dI[2], dI[3]);
        }
    }
    __syncthreads();   // Y complete

    // =============== Stage 3: truncated irfft (folded, FFMA-imm) ===============
    {
        const int op = tid & 31;
        const int pp = tid >> 5;

        for (int pass = 0; pass < 2; pass++) {
            const int p   = pp + pass * 8;
            const int col = op ^ ((p & 3) << 2);   // u64 col (swizzled)

            float yRL[16], yRH[16], yIL[16], yIH[16];
#pragma unroll
            for (int m = 0; m < 16; m++) {
                unpack2(XY64[((2 * m)     * TILE_P + p) * 32 + col], yRL[m], yRH[m]);
                unpack2(XY64[((2 * m + 1) * TILE_P + p) * 32 + col], yIL[m], yIH[m]);
            }

            u64* outp = reinterpret_cast<u64*>(out) + (long)(p0 + p) * 32 + op;

            // t = 0
            {
                float c0 = 0.0f, c1 = 0.0f;
#pragma unroll
                for (int m = 0; m < 16; m++) {
                    const float gc = alpha64(m);
                    c0 = fmaf(yRL[m], gc, c0);
                    c1 = fmaf(yRH[m], gc, c1);
                }
                outp[0] = pack2(c0, c1);
            }
            // t = 32
            {
                float c0 = 0.0f, c1 = 0.0f;
#pragma unroll
                for (int m = 0; m < 16; m++) {
                    const float gc = (m & 1) ? -alpha64(m) : alpha64(m);
                    c0 = fmaf(yRL[m], gc, c0);
                    c1 = fmaf(yRH[m], gc, c1);
                }
                outp[32 * (SCOL / 2)] = pack2(c0, c1);
            }

#pragma unroll
            for (int t = 1; t < 32; t++) {
                float C0 = 0.0f, C1 = 0.0f, S0 = 0.0f, S1 = 0.0f;
#pragma unroll
                for (int m = 0; m < 16; m++) {
                    const float gc = alpha64(m) * cos64(m * t);
                    const float gs = alpha64(m) * cos64(m * t + 16);
                    if (gc != 0.0f) {
                        C0 = fmaf(yRL[m], gc, C0);
                        C1 = fmaf(yRH[m], gc, C1);
                    }
                    if (gs != 0.0f) {
                        S0 = fmaf(yIL[m], gs, S0);
                        S1 = fmaf(yIH[m], gs, S1);
                    }
                }
                outp[(long)t * (SCOL / 2)]        = pack2(C0 + S0, C1 + S1);
                outp[(long)(64 - t) * (SCOL / 2)] = pack2(C0 - S0, C1 - S1);
            }
        }
    }
}

// =====================================================================
extern "C" void kernel_launch(void* const* d_in, const int* in_sizes, int n_in,
                              void* d_out, int out_size) {
    const float* x = (const float*)d_in[0];   // [64][1024][16][64] f32
    const float* w = (const float*)d_in[1];   // [64][64][16][2] f32
    float* out     = (float*)d_out;           // [64][1024][16][64] f32
    (void)in_sizes; (void)n_in; (void)out_size;

    cudaFuncSetAttribute(fused_spectral, cudaFuncAttributeMaxDynamicSharedMemorySize, 196608);

    w_pack<<<512, 256>>>(w);
    fused_spectral<<<NBLK, NTHR, 196608>>>(x, out);
}

// round 15
// speedup vs baseline: 1.8569x; 1.0885x over previous
#include <cuda_runtime.h>
#include <cstdint>

// Problem constants
#define TD     64
#define MODES  16
#define MRI    32          // 2*MODES
#define PD     16384       // N*D pixels
#define SCOL   1048576     // PD*64 floats per time row
#define TILE_P 16
#define NBLK   (PD / TILE_P)   // 1024 CTAs
#define NTHR   256

typedef unsigned long long u64;

// tf32-rounded, k-permuted, n-swizzled weights:
// g_W3f[m][comp][n][ S(k) ^ ((n&3)<<3) ], comp 0=WR, 1=WI.  512 KB, L2-resident.
__device__ __align__(16) float g_W3f[MODES * 2 * 64 * 64];

// ---------- compile-time DFT coefficients ----------
__host__ __device__ constexpr float cos64(int k) {
    constexpr float COSQ[17] = {
        1.0f,
        0.995184726672197f, 0.980785280403230f, 0.956940335732209f,
        0.923879532511287f, 0.881921264348355f, 0.831469612302545f,
        0.773010453362737f, 0.707106781186548f, 0.634393284163645f,
        0.555570233019602f, 0.471396736825998f, 0.382683432365090f,
        0.290284677254462f, 0.195090322016128f, 0.098017140329561f,
        0.0f
    };
    k &= 63;
    float s = 1.0f;
    if (k > 32) k = 64 - k;
    if (k > 16) { k = 32 - k; s = -1.0f; }
    return s * COSQ[k];
}
__host__ __device__ constexpr float alpha64(int m) {
    return ((m == 0) ? 1.0f : 2.0f) / 64.0f;
}

// mma-fragment channel permutation within each 8-wide k-tile:
// logical r<4 -> 2r ; r>=4 -> 2(r-4)+1   (pairs (t, t+4) become adjacent)
__host__ __device__ __forceinline__ int SPERM(int c) {
    int r = c & 7;
    int s = (r < 4) ? (2 * r) : (2 * (r - 4) + 1);
    return (c & ~7) | s;
}

// ---------- helpers ----------
__device__ __forceinline__ u64 pack2(float a, float b) {
    u64 r;
    asm("mov.b64 %0, {%1, %2};" : "=l"(r) : "f"(a), "f"(b));
    return r;
}
__device__ __forceinline__ void unpack2(u64 v, float &lo, float &hi) {
    asm("mov.b64 {%0, %1}, %2;" : "=f"(lo), "=f"(hi) : "l"(v));
}
__device__ __forceinline__ uint32_t f2tf32(float x) {
    uint32_t r;
    asm("cvt.rna.tf32.f32 %0, %1;" : "=r"(r) : "f"(x));
    return r;
}
__device__ __forceinline__ void mma_tf32(float d[4],
                                         uint32_t a0, uint32_t a1, uint32_t a2, uint32_t a3,
                                         uint32_t b0, uint32_t b1) {
    asm("mma.sync.aligned.m16n8k8.row.col.f32.tf32.tf32.f32 "
        "{%0,%1,%2,%3},{%4,%5,%6,%7},{%8,%9},{%0,%1,%2,%3};"
        : "+f"(d[0]), "+f"(d[1]), "+f"(d[2]), "+f"(d[3])
        : "r"(a0), "r"(a1), "r"(a2), "r"(a3), "r"(b0), "r"(b1));
}

// =====================================================================
// One-time weight repack into the fragment-ready image (same as R14).
// =====================================================================
__global__ void __launch_bounds__(256) w_pack(const float* __restrict__ w) {
    int idx = blockIdx.x * 256 + threadIdx.x;         // 0 .. 131071
    int m    = idx >> 13;
    int comp = (idx >> 12) & 1;
    int n    = (idx >> 6) & 63;
    int k    = idx & 63;
    float v = w[(((long)k * 64 + n) * MODES + m) * 2 + comp];
    int dst = m * 8192 + (comp * 64 + n) * 64 + (SPERM(k) ^ ((n & 3) << 3));
    reinterpret_cast<uint32_t*>(g_W3f)[dst] = f2tf32(v);
}

// =====================================================================
// Fused spectral conv. 256 threads, 16 pixels/CTA, 128 KB smem.
// smem: XY [32 mri][16 px][64 f32]
//   X rows: tf32 bits, k-permuted cols, XOR-swizzled by (px&3)<<3 (f32 units)
//   Y rows: f32, logical cols, XOR-swizzled by (px&3)<<3
// Stage 2: warp owns 2 modes end-to-end (M=16px, N=64o, K=64c) — zero
// barriers; W fragments streamed from gmem (L2-resident).
// Only 2 __syncthreads in the whole kernel.
// =====================================================================
__global__ void __launch_bounds__(NTHR, 1) fused_spectral(const float* __restrict__ x,
                                                          float* __restrict__ out) {
    extern __shared__ __align__(16) char smem[];
    u64*      XY64 = reinterpret_cast<u64*>(smem);
    uint32_t* XYu  = reinterpret_cast<uint32_t*>(smem);

    const int tid = threadIdx.x;
    const int p0  = blockIdx.x * TILE_P;

    // =============== Stage 1: truncated rfft (folded, FFMA-imm) ===============
    {
        const int cp = tid & 31;
        const int pp = tid >> 5;
        const int s0 = SPERM(2 * cp);
        const int s1 = SPERM(2 * cp + 1);

        for (int pass = 0; pass < 2; pass++) {
            const int p   = pp + pass * 8;
            const int swz = (p & 3) << 3;
            const u64* xp = reinterpret_cast<const u64*>(x) + (long)(p0 + p) * 32 + cp;

            float XcL[16], XcH[16], XsL[16], XsH[16];
            {
                float x0L, x0H, x32L, x32H;
                unpack2(xp[0], x0L, x0H);
                unpack2(xp[32 * (SCOL / 2)], x32L, x32H);
#pragma unroll
                for (int m = 0; m < 16; m++) {
                    if (m & 1) { XcL[m] = x0L - x32L; XcH[m] = x0H - x32H; }
                    else       { XcL[m] = x0L + x32L; XcH[m] = x0H + x32H; }
                    XsL[m] = 0.0f; XsH[m] = 0.0f;
                }
            }

#pragma unroll
            for (int t = 1; t < 32; t++) {
                float aL, aH, bL, bH;
                unpack2(xp[(long)t * (SCOL / 2)], aL, aH);
                unpack2(xp[(long)(64 - t) * (SCOL / 2)], bL, bH);
                const float eL = aL + bL, eH = aH + bH;
                const float oL = aL - bL, oH = aH - bH;
                XcL[0] += eL; XcH[0] += eH;
#pragma unroll
                for (int m = 1; m < 16; m++) {
                    const float fc = cos64(m * t);
                    const float fs = cos64(m * t + 16);
                    if (fc != 0.0f) {
                        XcL[m] = fmaf(eL, fc, XcL[m]);
                        XcH[m] = fmaf(eH, fc, XcH[m]);
                    }
                    if (fs != 0.0f) {
                        XsL[m] = fmaf(oL, fs, XsL[m]);
                        XsH[m] = fmaf(oH, fs, XsH[m]);
                    }
                }
            }

#pragma unroll
            for (int m = 0; m < 16; m++) {
                const int rowR = ((2 * m)     * TILE_P + p) * 64;
                const int rowI = ((2 * m + 1) * TILE_P + p) * 64;
                XYu[rowR + (s0 ^ swz)] = f2tf32(XcL[m]);
                XYu[rowR + (s1 ^ swz)] = f2tf32(XcH[m]);
                XYu[rowI + (s0 ^ swz)] = f2tf32(XsL[m]);
                XYu[rowI + (s1 ^ swz)] = f2tf32(XsH[m]);
            }
        }
    }

    __syncthreads();   // X published (sync #1)

    // =============== Stage 2: complex channel mix (tensor, barrier-free) ===============
    // Warp w owns modes 2w, 2w+1. YR = XR*WR + XI*(-WI); YI = XR*WI + XI*WR.
    {
        const int lane = tid & 31;
        const int wrp  = tid >> 5;
        const int g    = lane >> 2;         // 0..7
        const int t    = lane & 3;          // 0..3
        const int swzg = (g & 3) << 2;      // u64-index XOR
        const u64* gW64 = reinterpret_cast<const u64*>(g_W3f);

#pragma unroll 1
        for (int mm = 0; mm < 2; mm++) {
            const int m = 2 * wrp + mm;
            const u64* Wm = gW64 + (long)m * 4096;
            const int rowR = (2 * m)     * TILE_P * 32;   // u64 base of XR rows
            const int rowI = (2 * m + 1) * TILE_P * 32;

            float dR[8][4], dI[8][4];
#pragma unroll
            for (int nt = 0; nt < 8; nt++)
#pragma unroll
                for (int j = 0; j < 4; j++) { dR[nt][j] = 0.f; dI[nt][j] = 0.f; }

#pragma unroll
            for (int kt = 0; kt < 8; kt++) {
                const int col = (kt * 4 + t) ^ swzg;
                u64 ar0 = XY64[rowR + g * 32 + col];
                u64 ar1 = XY64[rowR + (g + 8) * 32 + col];
                u64 ai0 = XY64[rowI + g * 32 + col];
                u64 ai1 = XY64[rowI + (g + 8) * 32 + col];
                uint2 AR0 = *reinterpret_cast<uint2*>(&ar0);
                uint2 AR1 = *reinterpret_cast<uint2*>(&ar1);
                uint2 AI0 = *reinterpret_cast<uint2*>(&ai0);
                uint2 AI1 = *reinterpret_cast<uint2*>(&ai1);

#pragma unroll
                for (int nt = 0; nt < 8; nt++) {
                    u64 br = __ldg(&Wm[(nt * 8 + g) * 32 + col]);        // WR (L2)
                    u64 bi = __ldg(&Wm[(64 + nt * 8 + g) * 32 + col]);   // WI (L2)
                    u64 bn = bi ^ 0x8000000080000000ULL;                 // -WI
                    uint2 BR = *reinterpret_cast<uint2*>(&br);
                    uint2 BI = *reinterpret_cast<uint2*>(&bi);
                    uint2 BN = *reinterpret_cast<uint2*>(&bn);

                    mma_tf32(dR[nt], AR0.x, AR1.x, AR0.y, AR1.y, BR.x, BR.y);
                    mma_tf32(dR[nt], AI0.x, AI1.x, AI0.y, AI1.y, BN.x, BN.y);
                    mma_tf32(dI[nt], AR0.x, AR1.x, AR0.y, AR1.y, BI.x, BI.y);
                    mma_tf32(dI[nt], AI0.x, AI1.x, AI0.y, AI1.y, BR.x, BR.y);
                }
            }

            // Epilogue: all X reads for this mode are done (D in regs) —
            // safe in-place overwrite, no barrier needed (rows private to warp).
#pragma unroll
            for (int nt = 0; nt < 8; nt++) {
                const int ecol = (nt * 4 + t) ^ swzg;
                XY64[rowR + g * 32 + ecol]       = pack2(dR[nt][0], dR[nt][1]);
                XY64[rowR + (g + 8) * 32 + ecol] = pack2(dR[nt][2], dR[nt][3]);
                XY64[rowI + g * 32 + ecol]       = pack2(dI[nt][0], dI[nt][1]);
                XY64[rowI + (g + 8) * 32 + ecol] = pack2(dI[nt][2], dI[nt][3]);
            }
        }
    }

    __syncthreads();   // Y complete (sync #2)

    // =============== Stage 3: truncated irfft (folded, FFMA-imm) ===============
    {
        const int op = tid & 31;
        const int pp = tid >> 5;

        for (int pass = 0; pass < 2; pass++) {
            const int p   = pp + pass * 8;
            const int col = op ^ ((p & 3) << 2);   // u64 col (swizzled)

            float yRL[16], yRH[16], yIL[16], yIH[16];
#pragma unroll
            for (int m = 0; m < 16; m++) {
                unpack2(XY64[((2 * m)     * TILE_P + p) * 32 + col], yRL[m], yRH[m]);
                unpack2(XY64[((2 * m + 1) * TILE_P + p) * 32 + col], yIL[m], yIH[m]);
            }

            u64* outp = reinterpret_cast<u64*>(out) + (long)(p0 + p) * 32 + op;

            // t = 0
            {
                float c0 = 0.0f, c1 = 0.0f;
#pragma unroll
                for (int m = 0; m < 16; m++) {
                    const float gc = alpha64(m);
                    c0 = fmaf(yRL[m], gc, c0);
                    c1 = fmaf(yRH[m], gc, c1);
                }
                outp[0] = pack2(c0, c1);
            }
            // t = 32
            {
                float c0 = 0.0f, c1 = 0.0f;
#pragma unroll
                for (int m = 0; m < 16; m++) {
                    const float gc = (m & 1) ? -alpha64(m) : alpha64(m);
                    c0 = fmaf(yRL[m], gc, c0);
                    c1 = fmaf(yRH[m], gc, c1);
                }
                outp[32 * (SCOL / 2)] = pack2(c0, c1);
            }

#pragma unroll
            for (int t = 1; t < 32; t++) {
                float C0 = 0.0f, C1 = 0.0f, S0 = 0.0f, S1 = 0.0f;
#pragma unroll
                for (int m = 0; m < 16; m++) {
                    const float gc = alpha64(m) * cos64(m * t);
                    const float gs = alpha64(m) * cos64(m * t + 16);
                    if (gc != 0.0f) {
                        C0 = fmaf(yRL[m], gc, C0);
                        C1 = fmaf(yRH[m], gc, C1);
                    }
                    if (gs != 0.0f) {
                        S0 = fmaf(yIL[m], gs, S0);
                        S1 = fmaf(yIH[m], gs, S1);
                    }
                }
                outp[(long)t * (SCOL / 2)]        = pack2(C0 + S0, C1 + S1);
                outp[(long)(64 - t) * (SCOL / 2)] = pack2(C0 - S0, C1 - S1);
            }
        }
    }
}

// =====================================================================
extern "C" void kernel_launch(void* const* d_in, const int* in_sizes, int n_in,
                              void* d_out, int out_size) {
    const float* x = (const float*)d_in[0];   // [64][1024][16][64] f32
    const float* w = (const float*)d_in[1];   // [64][64][16][2] f32
    float* out     = (float*)d_out;           // [64][1024][16][64] f32
    (void)in_sizes; (void)n_in; (void)out_size;

    cudaFuncSetAttribute(fused_spectral, cudaFuncAttributeMaxDynamicSharedMemorySize, 131072);

    w_pack<<<512, 256>>>(w);
    fused_spectral<<<NBLK, NTHR, 131072>>>(x, out);
}

// round 16
// speedup vs baseline: 2.3631x; 1.2726x over previous
#include <cuda_runtime.h>
#include <cstdint>

// Problem constants
#define TD     64
#define MODES  16
#define MRI    32          // 2*MODES
#define PD     16384       // N*D pixels
#define SCOL   1048576     // PD*64 floats per time row
#define TILE_P 16
#define NBLK   (PD / TILE_P)   // 1024 CTAs
#define NTHR   512

typedef unsigned long long u64;

// tf32-rounded, k-permuted, n-swizzled weights:
// g_W3f[m][comp][n][ S(k) ^ ((n&3)<<3) ], comp 0=WR, 1=WI.  512 KB, L2-resident.
__device__ __align__(16) float g_W3f[MODES * 2 * 64 * 64];

// ---------- compile-time DFT coefficients ----------
__host__ __device__ constexpr float cos64(int k) {
    constexpr float COSQ[17] = {
        1.0f,
        0.995184726672197f, 0.980785280403230f, 0.956940335732209f,
        0.923879532511287f, 0.881921264348355f, 0.831469612302545f,
        0.773010453362737f, 0.707106781186548f, 0.634393284163645f,
        0.555570233019602f, 0.471396736825998f, 0.382683432365090f,
        0.290284677254462f, 0.195090322016128f, 0.098017140329561f,
        0.0f
    };
    k &= 63;
    float s = 1.0f;
    if (k > 32) k = 64 - k;
    if (k > 16) { k = 32 - k; s = -1.0f; }
    return s * COSQ[k];
}
__host__ __device__ constexpr float alpha64(int m) {
    return ((m == 0) ? 1.0f : 2.0f) / 64.0f;
}

// mma-fragment channel permutation within each 8-wide k-tile:
// logical r<4 -> 2r ; r>=4 -> 2(r-4)+1
__host__ __device__ __forceinline__ int SPERM(int c) {
    int r = c & 7;
    int s = (r < 4) ? (2 * r) : (2 * (r - 4) + 1);
    return (c & ~7) | s;
}

// ---------- helpers ----------
__device__ __forceinline__ u64 pack2(float a, float b) {
    u64 r;
    asm("mov.b64 %0, {%1, %2};" : "=l"(r) : "f"(a), "f"(b));
    return r;
}
__device__ __forceinline__ void unpack2(u64 v, float &lo, float &hi) {
    asm("mov.b64 {%0, %1}, %2;" : "=f"(lo), "=f"(hi) : "l"(v));
}
__device__ __forceinline__ uint32_t f2tf32(float x) {
    uint32_t r;
    asm("cvt.rna.tf32.f32 %0, %1;" : "=r"(r) : "f"(x));
    return r;
}
__device__ __forceinline__ void mma_tf32(float d[4],
                                         uint32_t a0, uint32_t a1, uint32_t a2, uint32_t a3,
                                         uint32_t b0, uint32_t b1) {
    asm("mma.sync.aligned.m16n8k8.row.col.f32.tf32.tf32.f32 "
        "{%0,%1,%2,%3},{%4,%5,%6,%7},{%8,%9},{%0,%1,%2,%3};"
        : "+f"(d[0]), "+f"(d[1]), "+f"(d[2]), "+f"(d[3])
        : "r"(a0), "r"(a1), "r"(a2), "r"(a3), "r"(b0), "r"(b1));
}

// =====================================================================
// One-time weight repack into the fragment-ready image.
// =====================================================================
__global__ void __launch_bounds__(256) w_pack(const float* __restrict__ w) {
    int idx = blockIdx.x * 256 + threadIdx.x;         // 0 .. 131071
    int m    = idx >> 13;
    int comp = (idx >> 12) & 1;
    int n    = (idx >> 6) & 63;
    int k    = idx & 63;
    float v = w[(((long)k * 64 + n) * MODES + m) * 2 + comp];
    int dst = m * 8192 + (comp * 64 + n) * 64 + (SPERM(k) ^ ((n & 3) << 3));
    reinterpret_cast<uint32_t*>(g_W3f)[dst] = f2tf32(v);
}

// =====================================================================
// Fused spectral conv. 512 threads, 16 pixels/CTA, 128 KB smem.
// smem: XY [32 mri][16 px][64 f32]
//   X rows: tf32 bits, k-permuted cols, XOR-swizzled by (px&3)<<3 (f32 units)
//   Y rows: f32, logical cols, XOR-swizzled by (px&3)<<3
// All stages single-pass (16 warps). Stage 2: warp owns 1 mode — zero
// barriers inside. Only 2 __syncthreads total.
// =====================================================================
__global__ void __launch_bounds__(NTHR, 1) fused_spectral(const float* __restrict__ x,
                                                          float* __restrict__ out) {
    extern __shared__ __align__(16) char smem[];
    u64*      XY64 = reinterpret_cast<u64*>(smem);
    uint32_t* XYu  = reinterpret_cast<uint32_t*>(smem);

    const int tid = threadIdx.x;
    const int p0  = blockIdx.x * TILE_P;

    // =============== Stage 1: truncated rfft (folded, FFMA-imm) ===============
    // 512 thr = 16 px x 32 channel-pairs, single pass.
    {
        const int cp = tid & 31;
        const int p  = tid >> 5;             // 0..15, warp-uniform
        const int s0 = SPERM(2 * cp);
        const int s1 = SPERM(2 * cp + 1);
        const int swz = (p & 3) << 3;
        const u64* xp = reinterpret_cast<const u64*>(x) + (long)(p0 + p) * 32 + cp;

        float XcL[16], XcH[16], XsL[16], XsH[16];
        {
            float x0L, x0H, x32L, x32H;
            unpack2(xp[0], x0L, x0H);
            unpack2(xp[32 * (SCOL / 2)], x32L, x32H);
#pragma unroll
            for (int m = 0; m < 16; m++) {
                if (m & 1) { XcL[m] = x0L - x32L; XcH[m] = x0H - x32H; }
                else       { XcL[m] = x0L + x32L; XcH[m] = x0H + x32H; }
                XsL[m] = 0.0f; XsH[m] = 0.0f;
            }
        }

#pragma unroll
        for (int t = 1; t < 32; t++) {
            float aL, aH, bL, bH;
            unpack2(xp[(long)t * (SCOL / 2)], aL, aH);
            unpack2(xp[(long)(64 - t) * (SCOL / 2)], bL, bH);
            const float eL = aL + bL, eH = aH + bH;
            const float oL = aL - bL, oH = aH - bH;
            XcL[0] += eL; XcH[0] += eH;
#pragma unroll
            for (int m = 1; m < 16; m++) {
                const float fc = cos64(m * t);
                const float fs = cos64(m * t + 16);
                if (fc != 0.0f) {
                    XcL[m] = fmaf(eL, fc, XcL[m]);
                    XcH[m] = fmaf(eH, fc, XcH[m]);
                }
                if (fs != 0.0f) {
                    XsL[m] = fmaf(oL, fs, XsL[m]);
                    XsH[m] = fmaf(oH, fs, XsH[m]);
                }
            }
        }

#pragma unroll
        for (int m = 0; m < 16; m++) {
            const int rowR = ((2 * m)     * TILE_P + p) * 64;
            const int rowI = ((2 * m + 1) * TILE_P + p) * 64;
            XYu[rowR + (s0 ^ swz)] = f2tf32(XcL[m]);
            XYu[rowR + (s1 ^ swz)] = f2tf32(XcH[m]);
            XYu[rowI + (s0 ^ swz)] = f2tf32(XsL[m]);
            XYu[rowI + (s1 ^ swz)] = f2tf32(XsH[m]);
        }
    }

    __syncthreads();   // X published (sync #1)

    // =============== Stage 2: complex channel mix (tensor, barrier-free) ===============
    // Warp w owns mode w. YR = XR*WR + XI*(-WI); YI = XR*WI + XI*WR.
    {
        const int lane = tid & 31;
        const int m    = tid >> 5;          // mode 0..15
        const int g    = lane >> 2;         // 0..7
        const int t    = lane & 3;          // 0..3
        const int swzg = (g & 3) << 2;      // u64-index XOR
        const u64* gW64 = reinterpret_cast<const u64*>(g_W3f);

        const u64* Wm = gW64 + (long)m * 4096;
        const int rowR = (2 * m)     * TILE_P * 32;   // u64 base of XR rows
        const int rowI = (2 * m + 1) * TILE_P * 32;

        float dR[8][4], dI[8][4];
#pragma unroll
        for (int nt = 0; nt < 8; nt++)
#pragma unroll
            for (int j = 0; j < 4; j++) { dR[nt][j] = 0.f; dI[nt][j] = 0.f; }

#pragma unroll
        for (int kt = 0; kt < 8; kt++) {
            const int col = (kt * 4 + t) ^ swzg;
            u64 ar0 = XY64[rowR + g * 32 + col];
            u64 ar1 = XY64[rowR + (g + 8) * 32 + col];
            u64 ai0 = XY64[rowI + g * 32 + col];
            u64 ai1 = XY64[rowI + (g + 8) * 32 + col];
            uint2 AR0 = *reinterpret_cast<uint2*>(&ar0);
            uint2 AR1 = *reinterpret_cast<uint2*>(&ar1);
            uint2 AI0 = *reinterpret_cast<uint2*>(&ai0);
            uint2 AI1 = *reinterpret_cast<uint2*>(&ai1);

#pragma unroll
            for (int nt = 0; nt < 8; nt++) {
                u64 br = __ldg(&Wm[(nt * 8 + g) * 32 + col]);        // WR (L2)
                u64 bi = __ldg(&Wm[(64 + nt * 8 + g) * 32 + col]);   // WI (L2)
                u64 bn = bi ^ 0x8000000080000000ULL;                 // -WI
                uint2 BR = *reinterpret_cast<uint2*>(&br);
                uint2 BI = *reinterpret_cast<uint2*>(&bi);
                uint2 BN = *reinterpret_cast<uint2*>(&bn);

                mma_tf32(dR[nt], AR0.x, AR1.x, AR0.y, AR1.y, BR.x, BR.y);
                mma_tf32(dR[nt], AI0.x, AI1.x, AI0.y, AI1.y, BN.x, BN.y);
                mma_tf32(dI[nt], AR0.x, AR1.x, AR0.y, AR1.y, BI.x, BI.y);
                mma_tf32(dI[nt], AI0.x, AI1.x, AI0.y, AI1.y, BR.x, BR.y);
            }
        }

        // Epilogue: all X reads for this mode done (D in regs) — safe
        // in-place overwrite, rows private to this warp.
#pragma unroll
        for (int nt = 0; nt < 8; nt++) {
            const int ecol = (nt * 4 + t) ^ swzg;
            XY64[rowR + g * 32 + ecol]       = pack2(dR[nt][0], dR[nt][1]);
            XY64[rowR + (g + 8) * 32 + ecol] = pack2(dR[nt][2], dR[nt][3]);
            XY64[rowI + g * 32 + ecol]       = pack2(dI[nt][0], dI[nt][1]);
            XY64[rowI + (g + 8) * 32 + ecol] = pack2(dI[nt][2], dI[nt][3]);
        }
    }

    __syncthreads();   // Y complete (sync #2)

    // =============== Stage 3: truncated irfft (folded, FFMA-imm) ===============
    // 512 thr = 16 px x 32 output-pairs, single pass.
    {
        const int op  = tid & 31;
        const int p   = tid >> 5;
        const int col = op ^ ((p & 3) << 2);   // u64 col (swizzled)

        float yRL[16], yRH[16], yIL[16], yIH[16];
#pragma unroll
        for (int m = 0; m < 16; m++) {
            unpack2(XY64[((2 * m)     * TILE_P + p) * 32 + col], yRL[m], yRH[m]);
            unpack2(XY64[((2 * m + 1) * TILE_P + p) * 32 + col], yIL[m], yIH[m]);
        }

        u64* outp = reinterpret_cast<u64*>(out) + (long)(p0 + p) * 32 + op;

        // t = 0
        {
            float c0 = 0.0f, c1 = 0.0f;
#pragma unroll
            for (int m = 0; m < 16; m++) {
                const float gc = alpha64(m);
                c0 = fmaf(yRL[m], gc, c0);
                c1 = fmaf(yRH[m], gc, c1);
            }
            outp[0] = pack2(c0, c1);
        }
        // t = 32
        {
            float c0 = 0.0f, c1 = 0.0f;
#pragma unroll
            for (int m = 0; m < 16; m++) {
                const float gc = (m & 1) ? -alpha64(m) : alpha64(m);
                c0 = fmaf(yRL[m], gc, c0);
                c1 = fmaf(yRH[m], gc, c1);
            }
            outp[32 * (SCOL / 2)] = pack2(c0, c1);
        }

#pragma unroll
        for (int t = 1; t < 32; t++) {
            float C0 = 0.0f, C1 = 0.0f, S0 = 0.0f, S1 = 0.0f;
#pragma unroll
            for (int m = 0; m < 16; m++) {
                const float gc = alpha64(m) * cos64(m * t);
                const float gs = alpha64(m) * cos64(m * t + 16);
                if (gc != 0.0f) {
                    C0 = fmaf(yRL[m], gc, C0);
                    C1 = fmaf(yRH[m], gc, C1);
                }
                if (gs != 0.0f) {
                    S0 = fmaf(yIL[m], gs, S0);
                    S1 = fmaf(yIH[m], gs, S1);
                }
            }
            outp[(long)t * (SCOL / 2)]        = pack2(C0 + S0, C1 + S1);
            outp[(long)(64 - t) * (SCOL / 2)] = pack2(C0 - S0, C1 - S1);
        }
    }
}

// =====================================================================
extern "C" void kernel_launch(void* const* d_in, const int* in_sizes, int n_in,
                              void* d_out, int out_size) {
    const float* x = (const float*)d_in[0];   // [64][1024][16][64] f32
    const float* w = (const float*)d_in[1];   // [64][64][16][2] f32
    float* out     = (float*)d_out;           // [64][1024][16][64] f32
    (void)in_sizes; (void)n_in; (void)out_size;

    cudaFuncSetAttribute(fused_spectral, cudaFuncAttributeMaxDynamicSharedMemorySize, 131072);

    w_pack<<<512, 256>>>(w);
    fused_spectral<<<NBLK, NTHR, 131072>>>(x, out);
}